// round 8
// baseline (speedup 1.0000x reference)
#include <cuda_runtime.h>
#include <math.h>

#define B_    64
#define T_    1280
#define PAST_ 1024
#define FUT_  256
#define D_    256
#define HID_  256

// ---------------- scratch (device globals; no allocations allowed) ----------------
__device__ float          d_u[(size_t)B_ * T_ * HID_];        // x @ W   (84 MB)
__device__ float          d_alpha[(size_t)B_ * FUT_ * PAST_]; // alpha / weights (64 MB)
__device__ int            d_cntf[FUT_];
__device__ unsigned short d_listf[FUT_ * PAST_];
__device__ unsigned int   d_mask32[FUT_ * 32];                // per-f bitmask over p
__device__ unsigned char  d_allow[FUT_ * PAST_];
__device__ int            d_cntc[PAST_];
__device__ unsigned char  d_listc[PAST_ * FUT_];              // per-p list of allowed f

// ---------------- row-softmax of A[PAST:, :PAST] over nonzeros; threshold 0.004 ----------------
__global__ void k_mask(const float* __restrict__ A) {
    __shared__ float ev[1024];
    __shared__ float red[256];
    __shared__ unsigned char alw[1024];
    int f = blockIdx.x, t = threadIdx.x;
    const float* row = A + (size_t)(PAST_ + f) * T_;

    float m = -INFINITY;
    for (int p = t; p < 1024; p += 256) {
        float a = row[p];
        ev[p] = a;
        if (a != 0.f) m = fmaxf(m, a);
    }
    red[t] = m; __syncthreads();
    for (int s = 128; s > 0; s >>= 1) { if (t < s) red[t] = fmaxf(red[t], red[t + s]); __syncthreads(); }
    m = red[0]; __syncthreads();

    float ls = 0.f;
    for (int p = t; p < 1024; p += 256) {
        float a = ev[p];
        float e = (a != 0.f) ? expf(a - m) : 0.f;
        ev[p] = e; ls += e;
    }
    red[t] = ls; __syncthreads();
    for (int s = 128; s > 0; s >>= 1) { if (t < s) red[t] += red[t + s]; __syncthreads(); }
    float sum = red[0];

    for (int p = t; p < 1024; p += 256) {
        float pv = ev[p] / sum;
        alw[p] = (ev[p] > 0.f && pv >= 0.004f) ? 1 : 0;
    }
    __syncthreads();
    if (t == 0) {
        int c = 0;
        unsigned int mw[32];
#pragma unroll
        for (int i = 0; i < 32; i++) mw[i] = 0u;
        for (int p = 0; p < 1024; p++) {
            d_allow[f * 1024 + p] = alw[p];
            if (alw[p]) {
                d_listf[f * 1024 + c] = (unsigned short)p;
                mw[p >> 5] |= (1u << (p & 31));
                c++;
            }
        }
        d_cntf[f] = c;
        for (int i = 0; i < 32; i++) d_mask32[f * 32 + i] = mw[i];
    }
}

// ---------------- per-column (p) lists of allowed f ----------------
__global__ void k_colmask() {
    int p = blockIdx.x * 256 + threadIdx.x;
    if (p < 1024) {
        int c = 0;
        for (int f = 0; f < 256; f++)
            if (d_allow[f * 1024 + p]) d_listc[p * 256 + c++] = (unsigned char)f;
        d_cntc[p] = c;
    }
}

// ---------------- u = x @ W : M=81920, N=256, K=256 fp32 SGEMM (double-buffered) ----------------
#define AP_ 129   // As row pad: cuts transpose-store conflicts 4-way -> 2-way
__global__ void __launch_bounds__(256, 2) k_gemm(const float* __restrict__ X,
                                                 const float* __restrict__ W) {
    __shared__ float As[2][16][AP_];
    __shared__ float Bs[2][16][128];
    int bm = blockIdx.x, bn = blockIdx.y;
    int t = threadIdx.x;
    int tx = t & 15, ty = t >> 4;

    const float* Ag = X + (size_t)bm * 128 * 256;
    const float* Bg = W + (size_t)bn * 128;

    // per-thread load coordinates (2 float4 each for A and B)
    int ar0 = t >> 2,          ac0 = (t & 3) << 2;
    int ar1 = (t + 256) >> 2,  ac1 = ((t + 256) & 3) << 2;
    int bk0 = t >> 5,          bn0 = (t & 31) << 2;
    int bk1 = (t + 256) >> 5,  bn1 = ((t + 256) & 31) << 2;

    float acc[8][8];
#pragma unroll
    for (int i = 0; i < 8; i++)
#pragma unroll
        for (int j = 0; j < 8; j++) acc[i][j] = 0.f;

    // prologue: tile 0 -> buffer 0
    {
        float4 va0 = *(const float4*)(Ag + (size_t)ar0 * 256 + ac0);
        float4 va1 = *(const float4*)(Ag + (size_t)ar1 * 256 + ac1);
        float4 vb0 = *(const float4*)(Bg + (size_t)bk0 * 256 + bn0);
        float4 vb1 = *(const float4*)(Bg + (size_t)bk1 * 256 + bn1);
        As[0][ac0 + 0][ar0] = va0.x; As[0][ac0 + 1][ar0] = va0.y;
        As[0][ac0 + 2][ar0] = va0.z; As[0][ac0 + 3][ar0] = va0.w;
        As[0][ac1 + 0][ar1] = va1.x; As[0][ac1 + 1][ar1] = va1.y;
        As[0][ac1 + 2][ar1] = va1.z; As[0][ac1 + 3][ar1] = va1.w;
        *(float4*)&Bs[0][bk0][bn0] = vb0;
        *(float4*)&Bs[0][bk1][bn1] = vb1;
    }
    __syncthreads();

    for (int kt = 0; kt < 256; kt += 16) {
        int cur = (kt >> 4) & 1;
        bool has_next = (kt + 16) < 256;

        float4 na0, na1, nb0, nb1;
        if (has_next) {
            int kn = kt + 16;
            na0 = *(const float4*)(Ag + (size_t)ar0 * 256 + kn + ac0);
            na1 = *(const float4*)(Ag + (size_t)ar1 * 256 + kn + ac1);
            nb0 = *(const float4*)(Bg + (size_t)(kn + bk0) * 256 + bn0);
            nb1 = *(const float4*)(Bg + (size_t)(kn + bk1) * 256 + bn1);
        }

#pragma unroll
        for (int k = 0; k < 16; k++) {
            float a[8], bb[8];
#pragma unroll
            for (int i = 0; i < 8; i++) a[i] = As[cur][k][ty * 8 + i];
            *(float4*)&bb[0] = *(float4*)&Bs[cur][k][tx * 8];
            *(float4*)&bb[4] = *(float4*)&Bs[cur][k][tx * 8 + 4];
#pragma unroll
            for (int i = 0; i < 8; i++)
#pragma unroll
                for (int j = 0; j < 8; j++) acc[i][j] = fmaf(a[i], bb[j], acc[i][j]);
        }

        if (has_next) {
            int nxt = 1 - cur;
            As[nxt][ac0 + 0][ar0] = na0.x; As[nxt][ac0 + 1][ar0] = na0.y;
            As[nxt][ac0 + 2][ar0] = na0.z; As[nxt][ac0 + 3][ar0] = na0.w;
            As[nxt][ac1 + 0][ar1] = na1.x; As[nxt][ac1 + 1][ar1] = na1.y;
            As[nxt][ac1 + 2][ar1] = na1.z; As[nxt][ac1 + 3][ar1] = na1.w;
            *(float4*)&Bs[nxt][bk0][bn0] = nb0;
            *(float4*)&Bs[nxt][bk1][bn1] = nb1;
            __syncthreads();
        }
    }

    float* Gp = d_u + ((size_t)bm * 128 + ty * 8) * 256 + bn * 128 + tx * 8;
#pragma unroll
    for (int i = 0; i < 8; i++) {
        *(float4*)(Gp + (size_t)i * 256)     = make_float4(acc[i][0], acc[i][1], acc[i][2], acc[i][3]);
        *(float4*)(Gp + (size_t)i * 256 + 4) = make_float4(acc[i][4], acc[i][5], acc[i][6], acc[i][7]);
    }
}

// ---------------- masked alpha: quad = ||u_f - u_p||^2, only allowed (f,p) pairs ----------------
__global__ void k_alpha(const float* __restrict__ SM) {
    __shared__ float u_s[32][256];
    int b = blockIdx.y, ft = blockIdx.x;
    int t = threadIdx.x, w = t >> 5, l = t & 31;

    float smv = SM[0];
    float sig = 1.f / (1.f + expf(-smv));
    float ns  = -0.5f / (sig * 0.01f);

    float uf[4][8];
    int fb = ft * 32 + w * 4;
#pragma unroll
    for (int ff = 0; ff < 4; ff++) {
        const float* ur = d_u + (size_t)(b * T_ + PAST_ + fb + ff) * 256;
#pragma unroll
        for (int k = 0; k < 8; k++) uf[ff][k] = ur[l + 32 * k];
    }

    for (int pt = 0; pt < 32; pt++) {
        __syncthreads();
#pragma unroll
        for (int i = 0; i < 8; i++) {
            int lin = t + i * 256;              // 2048 float4
            int r = lin >> 6, c = (lin & 63) << 2;
            *(float4*)&u_s[r][c] =
                *(const float4*)(d_u + ((size_t)(b * T_ + pt * 32 + r)) * 256 + c);
        }
        __syncthreads();
#pragma unroll
        for (int ff = 0; ff < 4; ff++) {
            int f = fb + ff;
            unsigned int m = d_mask32[f * 32 + pt];
            while (m) {
                int bit = __ffs(m) - 1; m &= m - 1;
                int p = pt * 32 + bit;
                float s = 0.f;
#pragma unroll
                for (int k = 0; k < 8; k++) {
                    float dif = uf[ff][k] - u_s[bit][l + 32 * k];
                    s = fmaf(dif, dif, s);
                }
#pragma unroll
                for (int o = 16; o; o >>= 1) s += __shfl_xor_sync(0xffffffffu, s, o);
                if (l == 0)
                    d_alpha[((size_t)(b * FUT_ + f)) * PAST_ + p] = s * ns;
            }
        }
    }
}

// ---------------- softmax over f (axis=1!) per (b,p) column, in-place ----------------
__global__ void k_colsm() {
    int b = blockIdx.y;
    int p = blockIdx.x * 8 + (threadIdx.x >> 5);
    int l = threadIdx.x & 31;
    int cnt = d_cntc[p];
    if (cnt == 0) return;
    const unsigned char* lst = d_listc + p * 256;
    float* base = d_alpha + (size_t)b * FUT_ * PAST_ + p;   // (b,f,p) at base + f*1024

    float m = -INFINITY;
    for (int k = l; k < cnt; k += 32) m = fmaxf(m, base[(size_t)lst[k] * 1024]);
#pragma unroll
    for (int o = 16; o; o >>= 1) m = fmaxf(m, __shfl_xor_sync(0xffffffffu, m, o));

    float s = 0.f;
    for (int k = l; k < cnt; k += 32) s += expf(base[(size_t)lst[k] * 1024] - m);
#pragma unroll
    for (int o = 16; o; o >>= 1) s += __shfl_xor_sync(0xffffffffu, s, o);

    float inv = 1.f / s;
    for (int k = l; k < cnt; k += 32) {
        size_t off = (size_t)lst[k] * 1024;
        base[off] = expf(base[off] - m) * inv;
    }
}

// ---------------- out[b,f,:] = sum_p w[b,f,p] * y[b,p,:]  (skip exact zeros) ----------------
__global__ void k_out(const float* __restrict__ Y, float* __restrict__ O) {
    __shared__ float wv[1024];
    __shared__ unsigned short pp[1024];
    int f = blockIdx.x, b = blockIdx.y, t = threadIdx.x;
    int cnt = d_cntf[f];
    const float* arow = d_alpha + ((size_t)(b * FUT_ + f)) * PAST_;
    for (int k = t; k < cnt; k += 256) {
        int p = d_listf[f * 1024 + k];
        pp[k] = (unsigned short)p;
        wv[k] = arow[p];
    }
    __syncthreads();
    float o = 0.f;
    for (int k = 0; k < cnt; k++) {
        float wk = wv[k];
        if (wk != 0.f)
            o = fmaf(wk, Y[((size_t)(b * PAST_ + pp[k])) * 256 + t], o);
    }
    O[((size_t)(b * FUT_ + f)) * 256 + t] = o;
}

// ---------------- launch ----------------
extern "C" void kernel_launch(void* const* d_in, const int* in_sizes, int n_in,
                              void* d_out, int out_size) {
    const float* x  = (const float*)d_in[0];
    const float* y  = (const float*)d_in[1];
    const float* A  = (const float*)d_in[2];
    const float* W  = (const float*)d_in[3];
    const float* sm = (const float*)d_in[4];
    float* out = (float*)d_out;

    k_mask   <<<256, 256>>>(A);
    k_colmask<<<4, 256>>>();
    k_gemm   <<<dim3(640, 2), 256>>>(x, W);
    k_alpha  <<<dim3(8, 64), 256>>>(sm);
    k_colsm  <<<dim3(128, 64), 256>>>();
    k_out    <<<dim3(256, 64), 256>>>(y, out);
}

// round 11
// speedup vs baseline: 1.0171x; 1.0171x over previous
#include <cuda_runtime.h>
#include <math.h>

#define B_    64
#define T_    1280
#define PAST_ 1024
#define FUT_  256
#define D_    256
#define HID_  256

// ---------------- scratch (device globals; no allocations allowed) ----------------
__device__ float          d_u[(size_t)B_ * T_ * HID_];        // x @ W   (84 MB)
__device__ float          d_alpha[(size_t)B_ * FUT_ * PAST_]; // alpha / weights (64 MB)
__device__ int            d_cntf[FUT_];
__device__ unsigned short d_listf[FUT_ * PAST_];
__device__ unsigned int   d_mask32[FUT_ * 32];                // per-f bitmask over p
__device__ unsigned char  d_allow[FUT_ * PAST_];
__device__ int            d_cntc[PAST_];
__device__ unsigned char  d_listc[PAST_ * FUT_];              // per-p list of allowed f
// tile pair lists: 8 f-tiles x 32 p-tiles, up to 512 pairs each (mean ~144, 32 sigma margin)
__device__ int            d_tcnt[256];
__device__ unsigned short d_tpair[256 * 512];                 // (fi<<5)|pi local indices

// ---------------- row-softmax of A[PAST:, :PAST] over nonzeros; threshold 0.004 ----------------
__global__ void k_mask(const float* __restrict__ A) {
    __shared__ float ev[1024];
    __shared__ float red[256];
    __shared__ unsigned char alw[1024];
    int f = blockIdx.x, t = threadIdx.x;
    const float* row = A + (size_t)(PAST_ + f) * T_;

    float m = -INFINITY;
    for (int p = t; p < 1024; p += 256) {
        float a = row[p];
        ev[p] = a;
        if (a != 0.f) m = fmaxf(m, a);
    }
    red[t] = m; __syncthreads();
    for (int s = 128; s > 0; s >>= 1) { if (t < s) red[t] = fmaxf(red[t], red[t + s]); __syncthreads(); }
    m = red[0]; __syncthreads();

    float ls = 0.f;
    for (int p = t; p < 1024; p += 256) {
        float a = ev[p];
        float e = (a != 0.f) ? expf(a - m) : 0.f;
        ev[p] = e; ls += e;
    }
    red[t] = ls; __syncthreads();
    for (int s = 128; s > 0; s >>= 1) { if (t < s) red[t] += red[t + s]; __syncthreads(); }
    float sum = red[0];

    for (int p = t; p < 1024; p += 256) {
        float pv = ev[p] / sum;
        alw[p] = (ev[p] > 0.f && pv >= 0.004f) ? 1 : 0;
    }
    __syncthreads();
    if (t == 0) {
        int c = 0;
        unsigned int mw[32];
#pragma unroll
        for (int i = 0; i < 32; i++) mw[i] = 0u;
        for (int p = 0; p < 1024; p++) {
            d_allow[f * 1024 + p] = alw[p];
            if (alw[p]) {
                d_listf[f * 1024 + c] = (unsigned short)p;
                mw[p >> 5] |= (1u << (p & 31));
                c++;
            }
        }
        d_cntf[f] = c;
        for (int i = 0; i < 32; i++) d_mask32[f * 32 + i] = mw[i];
    }
}

// ---------------- per-column (p) lists of allowed f ----------------
__global__ void k_colmask() {
    int p = blockIdx.x * 256 + threadIdx.x;
    if (p < 1024) {
        int c = 0;
        for (int f = 0; f < 256; f++)
            if (d_allow[f * 1024 + p]) d_listc[p * 256 + c++] = (unsigned char)f;
        d_cntc[p] = c;
    }
}

// ---------------- compact per-tile (32f x 32p) pair lists from the bitmask ----------------
__global__ void k_tiles() {   // grid (8, 32), block 32
    int ft = blockIdx.x, pt = blockIdx.y;
    int fi = threadIdx.x;                          // 0..31
    unsigned int w = d_mask32[(ft * 32 + fi) * 32 + pt];
    int n = __popc(w);
    int inc = n;
#pragma unroll
    for (int d = 1; d < 32; d <<= 1) {
        int v = __shfl_up_sync(0xffffffffu, inc, d);
        if (fi >= d) inc += v;
    }
    int excl = inc - n;
    if (fi == 31) d_tcnt[ft * 32 + pt] = (inc < 512) ? inc : 512;
    unsigned short* dst = d_tpair + (ft * 32 + pt) * 512;
    int c = excl;
    while (w) {
        int bit = __ffs(w) - 1; w &= w - 1;
        if (c < 512) dst[c] = (unsigned short)((fi << 5) | bit);
        c++;
    }
}

// ---------------- u = x @ W : M=81920, N=256, K=256 fp32 SGEMM (double-buffered) ----------------
#define AP_ 129
__global__ void __launch_bounds__(256, 2) k_gemm(const float* __restrict__ X,
                                                 const float* __restrict__ W) {
    __shared__ float As[2][16][AP_];
    __shared__ float Bs[2][16][128];
    int bm = blockIdx.x, bn = blockIdx.y;
    int t = threadIdx.x;
    int tx = t & 15, ty = t >> 4;

    const float* Ag = X + (size_t)bm * 128 * 256;
    const float* Bg = W + (size_t)bn * 128;

    int ar0 = t >> 2,          ac0 = (t & 3) << 2;
    int ar1 = (t + 256) >> 2,  ac1 = ((t + 256) & 3) << 2;
    int bk0 = t >> 5,          bn0 = (t & 31) << 2;
    int bk1 = (t + 256) >> 5,  bn1 = ((t + 256) & 31) << 2;

    float acc[8][8];
#pragma unroll
    for (int i = 0; i < 8; i++)
#pragma unroll
        for (int j = 0; j < 8; j++) acc[i][j] = 0.f;

    {
        float4 va0 = *(const float4*)(Ag + (size_t)ar0 * 256 + ac0);
        float4 va1 = *(const float4*)(Ag + (size_t)ar1 * 256 + ac1);
        float4 vb0 = *(const float4*)(Bg + (size_t)bk0 * 256 + bn0);
        float4 vb1 = *(const float4*)(Bg + (size_t)bk1 * 256 + bn1);
        As[0][ac0 + 0][ar0] = va0.x; As[0][ac0 + 1][ar0] = va0.y;
        As[0][ac0 + 2][ar0] = va0.z; As[0][ac0 + 3][ar0] = va0.w;
        As[0][ac1 + 0][ar1] = va1.x; As[0][ac1 + 1][ar1] = va1.y;
        As[0][ac1 + 2][ar1] = va1.z; As[0][ac1 + 3][ar1] = va1.w;
        *(float4*)&Bs[0][bk0][bn0] = vb0;
        *(float4*)&Bs[0][bk1][bn1] = vb1;
    }
    __syncthreads();

    for (int kt = 0; kt < 256; kt += 16) {
        int cur = (kt >> 4) & 1;
        bool has_next = (kt + 16) < 256;

        float4 na0, na1, nb0, nb1;
        if (has_next) {
            int kn = kt + 16;
            na0 = *(const float4*)(Ag + (size_t)ar0 * 256 + kn + ac0);
            na1 = *(const float4*)(Ag + (size_t)ar1 * 256 + kn + ac1);
            nb0 = *(const float4*)(Bg + (size_t)(kn + bk0) * 256 + bn0);
            nb1 = *(const float4*)(Bg + (size_t)(kn + bk1) * 256 + bn1);
        }

#pragma unroll
        for (int k = 0; k < 16; k++) {
            float a[8], bb[8];
#pragma unroll
            for (int i = 0; i < 8; i++) a[i] = As[cur][k][ty * 8 + i];
            *(float4*)&bb[0] = *(float4*)&Bs[cur][k][tx * 8];
            *(float4*)&bb[4] = *(float4*)&Bs[cur][k][tx * 8 + 4];
#pragma unroll
            for (int i = 0; i < 8; i++)
#pragma unroll
                for (int j = 0; j < 8; j++) acc[i][j] = fmaf(a[i], bb[j], acc[i][j]);
        }

        if (has_next) {
            int nxt = 1 - cur;
            As[nxt][ac0 + 0][ar0] = na0.x; As[nxt][ac0 + 1][ar0] = na0.y;
            As[nxt][ac0 + 2][ar0] = na0.z; As[nxt][ac0 + 3][ar0] = na0.w;
            As[nxt][ac1 + 0][ar1] = na1.x; As[nxt][ac1 + 1][ar1] = na1.y;
            As[nxt][ac1 + 2][ar1] = na1.z; As[nxt][ac1 + 3][ar1] = na1.w;
            *(float4*)&Bs[nxt][bk0][bn0] = nb0;
            *(float4*)&Bs[nxt][bk1][bn1] = nb1;
            __syncthreads();
        }
    }

    float* Gp = d_u + ((size_t)bm * 128 + ty * 8) * 256 + bn * 128 + tx * 8;
#pragma unroll
    for (int i = 0; i < 8; i++) {
        *(float4*)(Gp + (size_t)i * 256)     = make_float4(acc[i][0], acc[i][1], acc[i][2], acc[i][3]);
        *(float4*)(Gp + (size_t)i * 256 + 4) = make_float4(acc[i][4], acc[i][5], acc[i][6], acc[i][7]);
    }
}

// ---------------- masked alpha: thread-per-pair, quad = ||u_f - u_p||^2 ----------------
// Reduction order replicates the R8 warp version bitwise:
//   partial s[j] = sum_{k=0..7} (d[j+32k])^2  (k ascending, fmaf chain)
//   fold s[j] += s[j+o] for o = 16,8,4,2,1    (same association as xor-shuffle tree)
#define UP_ 260
__global__ void __launch_bounds__(256) k_alpha(const float* __restrict__ SM) {
    extern __shared__ float dynsm[];
    float (*uf_s)[UP_] = (float (*)[UP_])dynsm;
    float (*up_s)[UP_] = (float (*)[UP_])(dynsm + 32 * UP_);

    int ft = blockIdx.x, b = blockIdx.y;
    int t = threadIdx.x;

    float smv = SM[0];
    float sig = 1.f / (1.f + expf(-smv));
    float ns  = -0.5f / (sig * 0.01f);

#pragma unroll
    for (int i = 0; i < 8; i++) {
        int lin = t + i * 256;              // 2048 float4
        int r = lin >> 6, c4 = lin & 63;
        *(float4*)&uf_s[r][c4 * 4] =
            *(const float4*)(d_u + ((size_t)(b * T_ + PAST_ + ft * 32 + r)) * 256 + c4 * 4);
    }

    for (int pt = 0; pt < 32; pt++) {
        __syncthreads();
#pragma unroll
        for (int i = 0; i < 8; i++) {
            int lin = t + i * 256;
            int r = lin >> 6, c4 = lin & 63;
            *(float4*)&up_s[r][c4 * 4] =
                *(const float4*)(d_u + ((size_t)(b * T_ + pt * 32 + r)) * 256 + c4 * 4);
        }
        __syncthreads();

        int cnt = d_tcnt[ft * 32 + pt];
        const unsigned short* pr = d_tpair + (size_t)(ft * 32 + pt) * 512;
        for (int base = 0; base < cnt; base += 256) {
            int idx = base + t;
            if (idx < cnt) {
                int pk = pr[idx];
                int fi = pk >> 5, pi = pk & 31;
                const float* fa = uf_s[fi];
                const float* pa = up_s[pi];
                float s[32];
#pragma unroll
                for (int j = 0; j < 32; j++) s[j] = 0.f;
                // m = element/4; partial index j = (m&7)*4 + i; k = m/8 ascends per partial
                for (int mo = 0; mo < 64; mo += 8) {
#pragma unroll
                    for (int mi = 0; mi < 8; mi++) {
                        int m = mo + mi;
                        float4 a  = *(const float4*)(fa + m * 4);
                        float4 bb = *(const float4*)(pa + m * 4);
                        float dx = a.x - bb.x, dy = a.y - bb.y;
                        float dz = a.z - bb.z, dw = a.w - bb.w;
                        s[mi * 4 + 0] = fmaf(dx, dx, s[mi * 4 + 0]);
                        s[mi * 4 + 1] = fmaf(dy, dy, s[mi * 4 + 1]);
                        s[mi * 4 + 2] = fmaf(dz, dz, s[mi * 4 + 2]);
                        s[mi * 4 + 3] = fmaf(dw, dw, s[mi * 4 + 3]);
                    }
                }
#pragma unroll
                for (int o = 16; o >= 1; o >>= 1)
#pragma unroll
                    for (int j = 0; j < o; j++) s[j] += s[j + o];

                int f = ft * 32 + fi, p = pt * 32 + pi;
                d_alpha[((size_t)(b * FUT_ + f)) * PAST_ + p] = s[0] * ns;
            }
        }
    }
}

// ---------------- softmax over f (axis=1!) per (b,p) column, in-place ----------------
__global__ void k_colsm() {
    int b = blockIdx.y;
    int p = blockIdx.x * 8 + (threadIdx.x >> 5);
    int l = threadIdx.x & 31;
    int cnt = d_cntc[p];
    if (cnt == 0) return;
    const unsigned char* lst = d_listc + p * 256;
    float* base = d_alpha + (size_t)b * FUT_ * PAST_ + p;

    float m = -INFINITY;
    for (int k = l; k < cnt; k += 32) m = fmaxf(m, base[(size_t)lst[k] * 1024]);
#pragma unroll
    for (int o = 16; o; o >>= 1) m = fmaxf(m, __shfl_xor_sync(0xffffffffu, m, o));

    float s = 0.f;
    for (int k = l; k < cnt; k += 32) s += expf(base[(size_t)lst[k] * 1024] - m);
#pragma unroll
    for (int o = 16; o; o >>= 1) s += __shfl_xor_sync(0xffffffffu, s, o);

    float inv = 1.f / s;
    for (int k = l; k < cnt; k += 32) {
        size_t off = (size_t)lst[k] * 1024;
        base[off] = expf(base[off] - m) * inv;
    }
}

// ---------------- out[b,f,:] = sum_p w[b,f,p] * y[b,p,:]  (skip exact zeros) ----------------
__global__ void k_out(const float* __restrict__ Y, float* __restrict__ O) {
    __shared__ float wv[1024];
    __shared__ unsigned short pp[1024];
    int f = blockIdx.x, b = blockIdx.y, t = threadIdx.x;
    int cnt = d_cntf[f];
    const float* arow = d_alpha + ((size_t)(b * FUT_ + f)) * PAST_;
    for (int k = t; k < cnt; k += 256) {
        int p = d_listf[f * 1024 + k];
        pp[k] = (unsigned short)p;
        wv[k] = arow[p];
    }
    __syncthreads();
    float o = 0.f;
    for (int k = 0; k < cnt; k++) {
        float wk = wv[k];
        if (wk != 0.f)
            o = fmaf(wk, Y[((size_t)(b * PAST_ + pp[k])) * 256 + t], o);
    }
    O[((size_t)(b * FUT_ + f)) * 256 + t] = o;
}

// ---------------- launch ----------------
extern "C" void kernel_launch(void* const* d_in, const int* in_sizes, int n_in,
                              void* d_out, int out_size) {
    const float* x  = (const float*)d_in[0];
    const float* y  = (const float*)d_in[1];
    const float* A  = (const float*)d_in[2];
    const float* W  = (const float*)d_in[3];
    const float* sm = (const float*)d_in[4];
    float* out = (float*)d_out;

    const int alpha_smem = 2 * 32 * UP_ * sizeof(float);   // 66560 B
    cudaFuncSetAttribute(k_alpha, cudaFuncAttributeMaxDynamicSharedMemorySize, alpha_smem);

    k_mask   <<<256, 256>>>(A);
    k_colmask<<<4, 256>>>();
    k_tiles  <<<dim3(8, 32), 32>>>();
    k_gemm   <<<dim3(640, 2), 256>>>(x, W);
    k_alpha  <<<dim3(8, 64), 256, alpha_smem>>>(sm);
    k_colsm  <<<dim3(128, 64), 256>>>();
    k_out    <<<dim3(256, 64), 256>>>(y, out);
}